// round 13
// baseline (speedup 1.0000x reference)
#include <cuda_runtime.h>
#include <math.h>

#define B_TOT   512
#define T_STEPS 2000
#define N_INP   32
#define N_HID   200
#define N_OUT   3
#define KDIM    (N_INP + N_HID)
#define NB      4
#define NCTA    (B_TOT / NB)
#define NTHR    256
#define VTH     1.0f

// per-CTA "did any of my 4 batches ever spike" flags (phase1 -> phase2)
__device__ unsigned g_flags[NCTA];

__device__ __forceinline__ float sigm(float v) { return 1.0f / (1.0f + expf(-v)); }

__device__ __forceinline__ unsigned long long pack_dup(float w) {
    unsigned long long r;
    asm("mov.b64 %0, {%1, %1};" : "=l"(r) : "f"(w));
    return r;
}
__device__ __forceinline__ void unpack2(unsigned long long v, float& lo, float& hi) {
    asm("mov.b64 {%0, %1}, %2;" : "=f"(lo), "=f"(hi) : "l"(v));
}
__device__ __forceinline__ unsigned long long fma_x2(unsigned long long a,
                                                     unsigned long long b,
                                                     unsigned long long c) {
    unsigned long long d;
    asm("fma.rn.f32x2 %0, %1, %2, %3;" : "=l"(d) : "l"(a), "l"(b), "l"(c));
    return d;
}
__device__ __forceinline__ unsigned long long mul_x2(unsigned long long a,
                                                     unsigned long long b) {
    unsigned long long d;
    asm("mul.rn.f32x2 %0, %1, %2;" : "=l"(d) : "l"(a), "l"(b));
    return d;
}
__device__ __forceinline__ unsigned long long add_x2(unsigned long long a,
                                                     unsigned long long b) {
    unsigned long long d;
    asm("add.rn.f32x2 %0, %1, %2;" : "=l"(d) : "l"(a), "l"(b));
    return d;
}

#define XG(bl, T) __ldg(xbase + (size_t)(bl) * (T_STEPS * N_INP) + (size_t)(T) * N_INP)

// ============================================================================
// Phase 1: zero-spike assumption, no inter-thread communication.
// Exact up to the first would-be spike -> max(mem1) > VTH is a sound detector.
// ============================================================================
__global__ void __launch_bounds__(NTHR, 1)
snn_detect_kernel(const float* __restrict__ x,
                  const float* __restrict__ W1,
                  const float* __restrict__ b1,
                  const float* __restrict__ tau_n,
                  const float* __restrict__ tau_m1,
                  const float* __restrict__ mask)
{
    __shared__ float4 xs4[4 * N_INP];   // 4-slot ring: x[t&3][i] packed over 4 batches

    const int tid  = threadIdx.x;
    const int wid  = tid >> 5;
    const int lane = tid & 31;
    const int b0   = blockIdx.x * NB;

    if (tid == 0) g_flags[blockIdx.x] = 0;

    const bool active = (tid < N_HID);
    unsigned long long wpk[N_INP];
    unsigned long long b1pk = 0ull, beta2 = 0ull, omb2 = 0ull, a12 = 0ull, oma12 = 0ull;
    if (active) {
        float beta = sigm(tau_n[tid]);
        float a1   = sigm(tau_m1[tid]);
        beta2 = pack_dup(beta);  omb2  = pack_dup(1.0f - beta);
        a12   = pack_dup(a1);    oma12 = pack_dup(1.0f - a1);
        b1pk  = pack_dup(b1[tid]);
#pragma unroll
        for (int i = 0; i < N_INP; ++i)
            wpk[i] = pack_dup(W1[tid * KDIM + i] * mask[tid * KDIM + i]);
    } else {
#pragma unroll
        for (int i = 0; i < N_INP; ++i) wpk[i] = 0ull;
    }

    // warp 7: x staging (slots 0,1 in smem; t=2,3 held in regs)
    const float* xbase = x + (size_t)b0 * (T_STEPS * N_INP) + lane;
    float4 rC = make_float4(0.f, 0.f, 0.f, 0.f), rD = rC;
    if (wid == 7) {
        float4 A, Bv;
        A.x  = XG(0,0); A.y  = XG(1,0); A.z  = XG(2,0); A.w  = XG(3,0);
        Bv.x = XG(0,1); Bv.y = XG(1,1); Bv.z = XG(2,1); Bv.w = XG(3,1);
        rC.x = XG(0,2); rC.y = XG(1,2); rC.z = XG(2,2); rC.w = XG(3,2);
        rD.x = XG(0,3); rD.y = XG(1,3); rD.z = XG(2,3); rD.w = XG(3,3);
        xs4[0 * N_INP + lane] = A;
        xs4[1 * N_INP + lane] = Bv;
    }
    __syncthreads();

    unsigned long long din01 = 0ull, din23 = 0ull, mem01 = 0ull, mem23 = 0ull;
    float mmax = 0.0f;

#pragma unroll 1
    for (int t = 0; t < T_STEPS; ++t) {
        if (wid < 7) {
            const ulonglong2* xv = (const ulonglong2*)(xs4 + (t & 3) * N_INP);
            // split accumulator chains (16 deep) to halve dependent latency
            unsigned long long a01 = b1pk, a23 = b1pk, c01 = 0ull, c23 = 0ull;
#pragma unroll
            for (int i = 0; i < 16; ++i) {
                ulonglong2 kv = xv[i];
                a01 = fma_x2(wpk[i], kv.x, a01);
                a23 = fma_x2(wpk[i], kv.y, a23);
            }
#pragma unroll
            for (int i = 16; i < 32; ++i) {
                ulonglong2 kv = xv[i];
                c01 = fma_x2(wpk[i], kv.x, c01);
                c23 = fma_x2(wpk[i], kv.y, c23);
            }
            unsigned long long cur01 = add_x2(a01, c01);
            unsigned long long cur23 = add_x2(a23, c23);

            // packed leak filters (spikes pinned to 0: no soft-reset term)
            din01 = fma_x2(beta2, din01, mul_x2(omb2, cur01));
            din23 = fma_x2(beta2, din23, mul_x2(omb2, cur23));
            mem01 = fma_x2(a12, mem01, mul_x2(oma12, din01));
            mem23 = fma_x2(a12, mem23, mul_x2(oma12, din23));

            float m0, m1, m2, m3;
            unpack2(mem01, m0, m1);
            unpack2(mem23, m2, m3);
            mmax = fmaxf(mmax, fmaxf(fmaxf(m0, m1), fmaxf(m2, m3)));
        } else {
            // warp 7: stage x(t+2) into ring slot, prefetch x(t+4)
            int tp2 = t + 2, tp4 = t + 4;
            if ((t & 1) == 0) {
                if (tp2 < T_STEPS) xs4[(tp2 & 3) * N_INP + lane] = rC;
                if (tp4 < T_STEPS) {
                    rC.x = XG(0,tp4); rC.y = XG(1,tp4);
                    rC.z = XG(2,tp4); rC.w = XG(3,tp4);
                }
            } else {
                if (tp2 < T_STEPS) xs4[(tp2 & 3) * N_INP + lane] = rD;
                if (tp4 < T_STEPS) {
                    rD.x = XG(0,tp4); rD.y = XG(1,tp4);
                    rD.z = XG(2,tp4); rD.w = XG(3,tp4);
                }
            }
        }
        __syncthreads();
    }

    unsigned bal = __ballot_sync(0xffffffffu, mmax > VTH);
    if (lane == 0 && bal) atomicOr(&g_flags[blockIdx.x], 1u);
}

// ============================================================================
// Phase 2: flag==0 -> closed-form output (bit-identical to zero-spike epilogue).
// flag!=0 -> full exact synchronized recurrence (R11 logic, recurrent weights
// read from global; correctness fallback, expected never to run).
// ============================================================================
__global__ void __launch_bounds__(NTHR, 1)
snn_solve_kernel(const float* __restrict__ x,
                 const float* __restrict__ W1,
                 const float* __restrict__ b1,
                 const float* __restrict__ tau_n,
                 const float* __restrict__ tau_m1,
                 const float* __restrict__ W2,
                 const float* __restrict__ b2,
                 const float* __restrict__ tau_m2,
                 const float* __restrict__ mask,
                 float* __restrict__ out)
{
    __shared__ float4   xs4[4 * N_INP];
    __shared__ unsigned summ[3 * 4];
    __shared__ unsigned msk[3 * 7 * 4];
    __shared__ float    red[N_OUT * NB * N_HID];

    const int tid  = threadIdx.x;
    const int wid  = tid >> 5;
    const int lane = tid & 31;
    const int b0   = blockIdx.x * NB;

    float a2v[N_OUT];
#pragma unroll
    for (int o = 0; o < N_OUT; ++o) a2v[o] = sigm(tau_m2[o]);

    if (g_flags[blockIdx.x] == 0u) {
        // zero spikes: s == 0 exactly -> out = b2[o] * Sc / T (bit-identical)
        if (tid < N_OUT * NB) {
            const int o = tid / NB;
            const int b = tid % NB;
            const float a   = a2v[o];
            const float aT  = powf(a, (float)T_STEPS);
            const float amT = a - aT;
            const float Sc  = amT + (float)(T_STEPS - 1) - amT / (1.0f - a);
            out[(size_t)(b0 + b) * N_OUT + o] = (0.0f + b2[o] * Sc) * (1.0f / (float)T_STEPS);
        }
        return;
    }

    // ---------------- exact fallback (never expected to execute) -------------
    if (tid < 12) summ[tid] = 0;

    const int  n       = tid;
    const bool active  = (n < N_HID);
    const bool is_comp = (wid < 7);

    float beta = 0.f, omb = 0.f, a1 = 0.f, oma1 = 0.f;
    unsigned long long wpk[N_INP];
    unsigned long long b1pk = 0ull;
    if (active) {
        beta = sigm(tau_n[n]);   omb  = 1.0f - beta;
        a1   = sigm(tau_m1[n]);  oma1 = 1.0f - a1;
        b1pk = pack_dup(b1[n]);
#pragma unroll
        for (int i = 0; i < N_INP; ++i)
            wpk[i] = pack_dup(W1[n * KDIM + i] * mask[n * KDIM + i]);
    } else {
#pragma unroll
        for (int i = 0; i < N_INP; ++i) wpk[i] = 0ull;
    }

    float mem1[NB] = {0.f,0.f,0.f,0.f};
    float din [NB] = {0.f,0.f,0.f,0.f};
    float spk [NB] = {0.f,0.f,0.f,0.f};
    float Us  [NB] = {0.f,0.f,0.f,0.f};
    float spk0[NB] = {0.f,0.f,0.f,0.f};
    float Wac[N_OUT][NB];
#pragma unroll
    for (int o = 0; o < N_OUT; ++o)
#pragma unroll
        for (int b = 0; b < NB; ++b) Wac[o][b] = 0.f;

    const float* xbase = x + (size_t)b0 * (T_STEPS * N_INP) + lane;
    float4 rC = make_float4(0.f,0.f,0.f,0.f), rD = rC;
    if (wid == 7) {
        float4 A, Bv;
        A.x  = XG(0,0); A.y  = XG(1,0); A.z  = XG(2,0); A.w  = XG(3,0);
        Bv.x = XG(0,1); Bv.y = XG(1,1); Bv.z = XG(2,1); Bv.w = XG(3,1);
        rC.x = XG(0,2); rC.y = XG(1,2); rC.z = XG(2,2); rC.w = XG(3,2);
        rD.x = XG(0,3); rD.y = XG(1,3); rD.z = XG(2,3); rD.w = XG(3,3);
        xs4[0 * N_INP + lane] = A;
        xs4[1 * N_INP + lane] = Bv;
    }
    __syncthreads();

    int pw = 0;
#pragma unroll 1
    for (int t = 0; t < T_STEPS; ++t) {
        int pz = pw + 1; if (pz == 3) pz = 0;
        int pr = pz + 1; if (pr == 3) pr = 0;

        if (is_comp) {
            unsigned long long acc01 = b1pk, acc23 = b1pk;
            const ulonglong2* xv = (const ulonglong2*)(xs4 + (t & 3) * N_INP);
#pragma unroll
            for (int i = 0; i < N_INP; ++i) {
                ulonglong2 kv = xv[i];
                acc01 = fma_x2(wpk[i], kv.x, acc01);
                acc23 = fma_x2(wpk[i], kv.y, acc23);
            }
            float cur[NB];
            unpack2(acc01, cur[0], cur[1]);
            unpack2(acc23, cur[2], cur[3]);

            uint4 sv = *(const uint4*)(summ + pr * 4);
            if (sv.x | sv.y | sv.z | sv.w) {
#pragma unroll
                for (int b = 0; b < NB; ++b) {
                    unsigned sb = (b == 0) ? sv.x : (b == 1) ? sv.y : (b == 2) ? sv.z : sv.w;
                    if (sb) {
#pragma unroll 1
                        for (int w = 0; w < 7; ++w) {
                            unsigned m = msk[(pr * 7 + w) * 4 + b];
                            while (m) {
                                int j = (w << 5) + __ffs(m) - 1;
                                m &= m - 1;
                                if (active)
                                    cur[b] += W1[n * KDIM + N_INP + j] *
                                              mask[n * KDIM + N_INP + j];
                            }
                        }
                    }
                }
            }

#pragma unroll
            for (int b = 0; b < NB; ++b) {
                din[b]  = fmaf(beta, din[b], omb * cur[b]);
                mem1[b] = fmaf(a1, mem1[b], oma1 * din[b]) - spk[b];
                spk[b]  = (mem1[b] > VTH) ? 1.0f : 0.0f;
            }

            unsigned bal0 = __ballot_sync(0xffffffffu, spk[0] > 0.f);
            unsigned bal1 = __ballot_sync(0xffffffffu, spk[1] > 0.f);
            unsigned bal2 = __ballot_sync(0xffffffffu, spk[2] > 0.f);
            unsigned bal3 = __ballot_sync(0xffffffffu, spk[3] > 0.f);
            if (lane < 4) {
                unsigned mw = (lane == 0) ? bal0 : (lane == 1) ? bal1
                            : (lane == 2) ? bal2 : bal3;
                msk[(pw * 7 + wid) * 4 + lane] = mw;
                if (mw) atomicOr(&summ[pw * 4 + lane], mw);
            }
            if (tid < 4) summ[pz * 4 + tid] = 0;

            if (t == 0) {
#pragma unroll
                for (int b = 0; b < NB; ++b) spk0[b] = spk[b];
            } else {
#pragma unroll
                for (int b = 0; b < NB; ++b) Us[b] += spk[b];
            }
#pragma unroll
            for (int o = 0; o < N_OUT; ++o)
#pragma unroll
                for (int b = 0; b < NB; ++b)
                    Wac[o][b] = fmaf(a2v[o], Wac[o][b], spk[b]);
        } else {
            int tp2 = t + 2, tp4 = t + 4;
            if ((t & 1) == 0) {
                if (tp2 < T_STEPS) xs4[(tp2 & 3) * N_INP + lane] = rC;
                if (tp4 < T_STEPS) {
                    rC.x = XG(0,tp4); rC.y = XG(1,tp4);
                    rC.z = XG(2,tp4); rC.w = XG(3,tp4);
                }
            } else {
                if (tp2 < T_STEPS) xs4[(tp2 & 3) * N_INP + lane] = rD;
                if (tp4 < T_STEPS) {
                    rD.x = XG(0,tp4); rD.y = XG(1,tp4);
                    rD.z = XG(2,tp4); rD.w = XG(3,tp4);
                }
            }
        }
        __syncthreads();
        pw = pz;
    }

    if (active) {
#pragma unroll
        for (int o = 0; o < N_OUT; ++o)
#pragma unroll
            for (int b = 0; b < NB; ++b)
                red[(o * NB + b) * N_HID + n] = Us[b] + a2v[o] * (spk0[b] - Wac[o][b]);
    }
    __syncthreads();

    if (tid < N_OUT * NB) {
        const int o = tid / NB;
        const int b = tid % NB;
        const float* Arow = red + tid * N_HID;
        const float* w2r  = W2 + o * N_HID;
        float s = 0.f;
#pragma unroll 8
        for (int j = 0; j < N_HID; ++j) s = fmaf(__ldg(w2r + j), Arow[j], s);

        const float a   = a2v[o];
        const float aT  = powf(a, (float)T_STEPS);
        const float amT = a - aT;
        const float Sc  = amT + (float)(T_STEPS - 1) - amT / (1.0f - a);

        out[(size_t)(b0 + b) * N_OUT + o] = (s + b2[o] * Sc) * (1.0f / (float)T_STEPS);
    }
}

extern "C" void kernel_launch(void* const* d_in, const int* in_sizes, int n_in,
                              void* d_out, int out_size) {
    const float* x      = (const float*)d_in[0];
    const float* W1     = (const float*)d_in[1];
    const float* b1     = (const float*)d_in[2];
    const float* tau_n  = (const float*)d_in[3];
    const float* tau_m1 = (const float*)d_in[4];
    const float* W2     = (const float*)d_in[5];
    const float* b2     = (const float*)d_in[6];
    const float* tau_m2 = (const float*)d_in[7];
    const float* mask   = (const float*)d_in[8];
    float*       out    = (float*)d_out;

    snn_detect_kernel<<<NCTA, NTHR>>>(x, W1, b1, tau_n, tau_m1, mask);
    snn_solve_kernel<<<NCTA, NTHR>>>(x, W1, b1, tau_n, tau_m1, W2, b2, tau_m2, mask, out);
}

// round 14
// speedup vs baseline: 1.9513x; 1.9513x over previous
#include <cuda_runtime.h>
#include <math.h>

#define B_TOT   512
#define T_STEPS 2000
#define N_INP   32
#define N_HID   200
#define N_OUT   3
#define KDIM    (N_INP + N_HID)
#define VTH     1.0f

// ---- detect kernel config: 256 CTAs x 256 thr, 2 batches/CTA, 2 CTAs/SM ----
#define DNB     2
#define DCTA    (B_TOT / DNB)      // 256
#define CHUNK   8                  // steps staged per barrier
#define NCHUNK  (T_STEPS / CHUNK)  // 250

// ---- solve kernel config (unchanged from R13) ----
#define NB      4
#define SCTA    (B_TOT / NB)       // 128
#define NTHR    256

// per-detect-CTA spike flags; solve CTA b reads flags[2b]|flags[2b+1]
__device__ unsigned g_flags[DCTA];

__device__ __forceinline__ float sigm(float v) { return 1.0f / (1.0f + expf(-v)); }

__device__ __forceinline__ unsigned long long pack_dup(float w) {
    unsigned long long r;
    asm("mov.b64 %0, {%1, %1};" : "=l"(r) : "f"(w));
    return r;
}
__device__ __forceinline__ unsigned long long pack2(float lo, float hi) {
    unsigned long long r;
    asm("mov.b64 %0, {%1, %2};" : "=l"(r) : "f"(lo), "f"(hi));
    return r;
}
__device__ __forceinline__ void unpack2(unsigned long long v, float& lo, float& hi) {
    asm("mov.b64 {%0, %1}, %2;" : "=f"(lo), "=f"(hi) : "l"(v));
}
__device__ __forceinline__ unsigned long long fma_x2(unsigned long long a,
                                                     unsigned long long b,
                                                     unsigned long long c) {
    unsigned long long d;
    asm("fma.rn.f32x2 %0, %1, %2, %3;" : "=l"(d) : "l"(a), "l"(b), "l"(c));
    return d;
}
__device__ __forceinline__ unsigned long long mul_x2(unsigned long long a,
                                                     unsigned long long b) {
    unsigned long long d;
    asm("mul.rn.f32x2 %0, %1, %2;" : "=l"(d) : "l"(a), "l"(b));
    return d;
}

// ============================================================================
// Phase 1 detector: spikes pinned to 0 (exact up to first would-be spike),
// no per-step communication. 2 CTAs/SM, 1 barrier per 8 steps.
// ============================================================================
__global__ void __launch_bounds__(256, 2)
snn_detect_kernel(const float* __restrict__ x,
                  const float* __restrict__ W1,
                  const float* __restrict__ b1,
                  const float* __restrict__ tau_n,
                  const float* __restrict__ tau_m1,
                  const float* __restrict__ mask)
{
    // xs[buf][step][ipair] = (x_i b0, x_{i+16} b0, x_i b1, x_{i+16} b1)
    __shared__ float4 xs[2][CHUNK][16];

    const int tid  = threadIdx.x;
    const int lane = tid & 31;
    const int b0   = blockIdx.x * DNB;

    if (tid == 0) g_flags[blockIdx.x] = 0;

    const bool active = (tid < N_HID);
    unsigned long long wpk[16];           // (w_i, w_{i+16}) pairs
    unsigned long long beta2 = 0ull, omb2 = 0ull, a12 = 0ull, oma12 = 0ull;
    float b1n = 0.f;
    if (active) {
        float beta = sigm(tau_n[tid]);
        float a1   = sigm(tau_m1[tid]);
        beta2 = pack_dup(beta);  omb2  = pack_dup(1.0f - beta);
        a12   = pack_dup(a1);    oma12 = pack_dup(1.0f - a1);
        b1n   = b1[tid];
#pragma unroll
        for (int i = 0; i < 16; ++i)
            wpk[i] = pack2(W1[tid * KDIM + i]      * mask[tid * KDIM + i],
                           W1[tid * KDIM + i + 16] * mask[tid * KDIM + i + 16]);
    } else {
#pragma unroll
        for (int i = 0; i < 16; ++i) wpk[i] = 0ull;
    }

    // staging map: each thread owns (batch bb, step-in-chunk ts, k-pair jl)
    const int jl = tid & 15;
    const int ts = (tid >> 4) & 7;
    const int bb = tid >> 7;
    const float* gb = x + ((size_t)(b0 + bb) * T_STEPS) * N_INP + jl;

    // prologue: stage chunk 0
    {
        float f0 = __ldg(gb + ts * N_INP);
        float f1 = __ldg(gb + ts * N_INP + 16);
        *(float2*)((float*)&xs[0][ts][jl] + 2 * bb) = make_float2(f0, f1);
    }
    __syncthreads();

    unsigned long long din01 = 0ull, mem01 = 0ull;
    float mmax0 = 0.f, mmax1 = 0.f;
    float f0 = 0.f, f1 = 0.f;

#pragma unroll 1
    for (int kc = 0; kc < NCHUNK; ++kc) {
        const int  buf  = kc & 1;
        const bool more = (kc + 1) < NCHUNK;

        // prefetch next chunk's x (latency hidden under the 8-step compute)
        if (more) {
            size_t off = (size_t)(kc + 1) * CHUNK * N_INP + (size_t)ts * N_INP;
            f0 = __ldg(gb + off);
            f1 = __ldg(gb + off + 16);
        }

#pragma unroll
        for (int s = 0; s < CHUNK; ++s) {
            const ulonglong2* xv = (const ulonglong2*)&xs[buf][s][0];
            // two 16-deep FFMA2 chains (one per batch); bias seeded in lane-lo
            unsigned long long a0 = pack2(b1n, 0.f);
            unsigned long long a1c = a0;
#pragma unroll
            for (int i = 0; i < 16; ++i) {
                ulonglong2 kv = xv[i];
                a0  = fma_x2(wpk[i], kv.x, a0);
                a1c = fma_x2(wpk[i], kv.y, a1c);
            }
            float l0, h0, l1, h1;
            unpack2(a0,  l0, h0);
            unpack2(a1c, l1, h1);
            unsigned long long cur01 = pack2(l0 + h0, l1 + h1);

            // packed leak filters (no soft-reset: spikes pinned to 0)
            din01 = fma_x2(beta2, din01, mul_x2(omb2,  cur01));
            mem01 = fma_x2(a12,   mem01, mul_x2(oma12, din01));

            float m0, m1;
            unpack2(mem01, m0, m1);
            mmax0 = fmaxf(mmax0, m0);
            mmax1 = fmaxf(mmax1, m1);
        }

        if (more)
            *(float2*)((float*)&xs[buf ^ 1][ts][jl] + 2 * bb) = make_float2(f0, f1);
        __syncthreads();
    }

    const float    mmax = fmaxf(mmax0, mmax1);
    const unsigned bal  = __ballot_sync(0xffffffffu, mmax > VTH);
    if (lane == 0 && bal) atomicOr(&g_flags[blockIdx.x], 1u);
}

// ============================================================================
// Phase 2: flags==0 -> closed-form output (bit-identical zero-spike epilogue).
// flags!=0 -> full exact synchronized recurrence (fallback, never expected).
// ============================================================================
__device__ __forceinline__ unsigned long long fma_x2s(unsigned long long a,
                                                      unsigned long long b,
                                                      unsigned long long c) {
    return fma_x2(a, b, c);
}

#define XG(bl, T) __ldg(xbase + (size_t)(bl) * (T_STEPS * N_INP) + (size_t)(T) * N_INP)

__global__ void __launch_bounds__(NTHR, 1)
snn_solve_kernel(const float* __restrict__ x,
                 const float* __restrict__ W1,
                 const float* __restrict__ b1,
                 const float* __restrict__ tau_n,
                 const float* __restrict__ tau_m1,
                 const float* __restrict__ W2,
                 const float* __restrict__ b2,
                 const float* __restrict__ tau_m2,
                 const float* __restrict__ mask,
                 float* __restrict__ out)
{
    __shared__ float4   xs4[4 * N_INP];
    __shared__ unsigned summ[3 * 4];
    __shared__ unsigned msk[3 * 7 * 4];
    __shared__ float    red[N_OUT * NB * N_HID];

    const int tid  = threadIdx.x;
    const int wid  = tid >> 5;
    const int lane = tid & 31;
    const int b0   = blockIdx.x * NB;

    float a2v[N_OUT];
#pragma unroll
    for (int o = 0; o < N_OUT; ++o) a2v[o] = sigm(tau_m2[o]);

    if ((g_flags[2 * blockIdx.x] | g_flags[2 * blockIdx.x + 1]) == 0u) {
        if (tid < N_OUT * NB) {
            const int o = tid / NB;
            const int b = tid % NB;
            const float a   = a2v[o];
            const float aT  = powf(a, (float)T_STEPS);
            const float amT = a - aT;
            const float Sc  = amT + (float)(T_STEPS - 1) - amT / (1.0f - a);
            out[(size_t)(b0 + b) * N_OUT + o] = (0.0f + b2[o] * Sc) * (1.0f / (float)T_STEPS);
        }
        return;
    }

    // ---------------- exact fallback (never expected to execute) -------------
    if (tid < 12) summ[tid] = 0;

    const int  n       = tid;
    const bool active  = (n < N_HID);
    const bool is_comp = (wid < 7);

    float beta = 0.f, omb = 0.f, a1 = 0.f, oma1 = 0.f;
    unsigned long long wpk[N_INP];
    unsigned long long b1pk = 0ull;
    if (active) {
        beta = sigm(tau_n[n]);   omb  = 1.0f - beta;
        a1   = sigm(tau_m1[n]);  oma1 = 1.0f - a1;
        b1pk = pack_dup(b1[n]);
#pragma unroll
        for (int i = 0; i < N_INP; ++i)
            wpk[i] = pack_dup(W1[n * KDIM + i] * mask[n * KDIM + i]);
    } else {
#pragma unroll
        for (int i = 0; i < N_INP; ++i) wpk[i] = 0ull;
    }

    float mem1[NB] = {0.f,0.f,0.f,0.f};
    float din [NB] = {0.f,0.f,0.f,0.f};
    float spk [NB] = {0.f,0.f,0.f,0.f};
    float Us  [NB] = {0.f,0.f,0.f,0.f};
    float spk0[NB] = {0.f,0.f,0.f,0.f};
    float Wac[N_OUT][NB];
#pragma unroll
    for (int o = 0; o < N_OUT; ++o)
#pragma unroll
        for (int b = 0; b < NB; ++b) Wac[o][b] = 0.f;

    const float* xbase = x + (size_t)b0 * (T_STEPS * N_INP) + lane;
    float4 rC = make_float4(0.f,0.f,0.f,0.f), rD = rC;
    if (wid == 7) {
        float4 A, Bv;
        A.x  = XG(0,0); A.y  = XG(1,0); A.z  = XG(2,0); A.w  = XG(3,0);
        Bv.x = XG(0,1); Bv.y = XG(1,1); Bv.z = XG(2,1); Bv.w = XG(3,1);
        rC.x = XG(0,2); rC.y = XG(1,2); rC.z = XG(2,2); rC.w = XG(3,2);
        rD.x = XG(0,3); rD.y = XG(1,3); rD.z = XG(2,3); rD.w = XG(3,3);
        xs4[0 * N_INP + lane] = A;
        xs4[1 * N_INP + lane] = Bv;
    }
    __syncthreads();

    int pw = 0;
#pragma unroll 1
    for (int t = 0; t < T_STEPS; ++t) {
        int pz = pw + 1; if (pz == 3) pz = 0;
        int pr = pz + 1; if (pr == 3) pr = 0;

        if (is_comp) {
            unsigned long long acc01 = b1pk, acc23 = b1pk;
            const ulonglong2* xv = (const ulonglong2*)(xs4 + (t & 3) * N_INP);
#pragma unroll
            for (int i = 0; i < N_INP; ++i) {
                ulonglong2 kv = xv[i];
                acc01 = fma_x2s(wpk[i], kv.x, acc01);
                acc23 = fma_x2s(wpk[i], kv.y, acc23);
            }
            float cur[NB];
            unpack2(acc01, cur[0], cur[1]);
            unpack2(acc23, cur[2], cur[3]);

            uint4 sv = *(const uint4*)(summ + pr * 4);
            if (sv.x | sv.y | sv.z | sv.w) {
#pragma unroll
                for (int b = 0; b < NB; ++b) {
                    unsigned sb = (b == 0) ? sv.x : (b == 1) ? sv.y : (b == 2) ? sv.z : sv.w;
                    if (sb) {
#pragma unroll 1
                        for (int w = 0; w < 7; ++w) {
                            unsigned m = msk[(pr * 7 + w) * 4 + b];
                            while (m) {
                                int j = (w << 5) + __ffs(m) - 1;
                                m &= m - 1;
                                if (active)
                                    cur[b] += W1[n * KDIM + N_INP + j] *
                                              mask[n * KDIM + N_INP + j];
                            }
                        }
                    }
                }
            }

#pragma unroll
            for (int b = 0; b < NB; ++b) {
                din[b]  = fmaf(beta, din[b], omb * cur[b]);
                mem1[b] = fmaf(a1, mem1[b], oma1 * din[b]) - spk[b];
                spk[b]  = (mem1[b] > VTH) ? 1.0f : 0.0f;
            }

            unsigned bal0 = __ballot_sync(0xffffffffu, spk[0] > 0.f);
            unsigned bal1 = __ballot_sync(0xffffffffu, spk[1] > 0.f);
            unsigned bal2 = __ballot_sync(0xffffffffu, spk[2] > 0.f);
            unsigned bal3 = __ballot_sync(0xffffffffu, spk[3] > 0.f);
            if (lane < 4) {
                unsigned mw = (lane == 0) ? bal0 : (lane == 1) ? bal1
                            : (lane == 2) ? bal2 : bal3;
                msk[(pw * 7 + wid) * 4 + lane] = mw;
                if (mw) atomicOr(&summ[pw * 4 + lane], mw);
            }
            if (tid < 4) summ[pz * 4 + tid] = 0;

            if (t == 0) {
#pragma unroll
                for (int b = 0; b < NB; ++b) spk0[b] = spk[b];
            } else {
#pragma unroll
                for (int b = 0; b < NB; ++b) Us[b] += spk[b];
            }
#pragma unroll
            for (int o = 0; o < N_OUT; ++o)
#pragma unroll
                for (int b = 0; b < NB; ++b)
                    Wac[o][b] = fmaf(a2v[o], Wac[o][b], spk[b]);
        } else {
            int tp2 = t + 2, tp4 = t + 4;
            if ((t & 1) == 0) {
                if (tp2 < T_STEPS) xs4[(tp2 & 3) * N_INP + lane] = rC;
                if (tp4 < T_STEPS) {
                    rC.x = XG(0,tp4); rC.y = XG(1,tp4);
                    rC.z = XG(2,tp4); rC.w = XG(3,tp4);
                }
            } else {
                if (tp2 < T_STEPS) xs4[(tp2 & 3) * N_INP + lane] = rD;
                if (tp4 < T_STEPS) {
                    rD.x = XG(0,tp4); rD.y = XG(1,tp4);
                    rD.z = XG(2,tp4); rD.w = XG(3,tp4);
                }
            }
        }
        __syncthreads();
        pw = pz;
    }

    if (active) {
#pragma unroll
        for (int o = 0; o < N_OUT; ++o)
#pragma unroll
            for (int b = 0; b < NB; ++b)
                red[(o * NB + b) * N_HID + n] = Us[b] + a2v[o] * (spk0[b] - Wac[o][b]);
    }
    __syncthreads();

    if (tid < N_OUT * NB) {
        const int o = tid / NB;
        const int b = tid % NB;
        const float* Arow = red + tid * N_HID;
        const float* w2r  = W2 + o * N_HID;
        float s = 0.f;
#pragma unroll 8
        for (int j = 0; j < N_HID; ++j) s = fmaf(__ldg(w2r + j), Arow[j], s);

        const float a   = a2v[o];
        const float aT  = powf(a, (float)T_STEPS);
        const float amT = a - aT;
        const float Sc  = amT + (float)(T_STEPS - 1) - amT / (1.0f - a);

        out[(size_t)(b0 + b) * N_OUT + o] = (s + b2[o] * Sc) * (1.0f / (float)T_STEPS);
    }
}

extern "C" void kernel_launch(void* const* d_in, const int* in_sizes, int n_in,
                              void* d_out, int out_size) {
    const float* x      = (const float*)d_in[0];
    const float* W1     = (const float*)d_in[1];
    const float* b1     = (const float*)d_in[2];
    const float* tau_n  = (const float*)d_in[3];
    const float* tau_m1 = (const float*)d_in[4];
    const float* W2     = (const float*)d_in[5];
    const float* b2     = (const float*)d_in[6];
    const float* tau_m2 = (const float*)d_in[7];
    const float* mask   = (const float*)d_in[8];
    float*       out    = (float*)d_out;

    snn_detect_kernel<<<DCTA, 256>>>(x, W1, b1, tau_n, tau_m1, mask);
    snn_solve_kernel<<<SCTA, NTHR>>>(x, W1, b1, tau_n, tau_m1, W2, b2, tau_m2, mask, out);
}

// round 15
// speedup vs baseline: 6.1866x; 3.1704x over previous
#include <cuda_runtime.h>
#include <math.h>

#define B_TOT   512
#define T_STEPS 2000
#define N_INP   32
#define N_HID   200
#define N_OUT   3
#define KDIM    (N_INP + N_HID)
#define VTH     1.0f
#define DET_TH  0.75f     // conservative detect threshold (true max ~0.4, spike => >=1.0)

// ---- detect kernel: 512 CTAs (1 batch each), tf32 MMA + chunked scan ----
#define DTHR    256
#define TC      64                 // time steps per chunk
#define NCH     32                 // 32*64 = 2048 >= 2000 (zero-padded tail)
#define XPAD    36                 // x row pad (words) -> conflict-free A frags
#define WPAD    36                 // W row pad (words) -> conflict-free B frags

#define SM_WS   (N_HID * WPAD)               // 7200 words: W as tf32
#define SM_XS   (2 * TC * XPAD)              // 4608 words: double-buffered x
#define SM_CUR  (TC * N_HID)                 // 12800 words: cur chunk
#define DET_SMEM_BYTES ((SM_WS + SM_XS + SM_CUR) * 4)   // 98432 B

// ---- solve kernel config (proven R14 path) ----
#define NB      4
#define SCTA    (B_TOT / NB)
#define NTHR    256

// per-batch spike flags (detect -> solve); solve CTA reads 4
__device__ unsigned g_flags[B_TOT];

__device__ __forceinline__ float sigm(float v) { return 1.0f / (1.0f + expf(-v)); }

__device__ __forceinline__ unsigned long long pack_dup(float w) {
    unsigned long long r;
    asm("mov.b64 %0, {%1, %1};" : "=l"(r) : "f"(w));
    return r;
}
__device__ __forceinline__ void unpack2(unsigned long long v, float& lo, float& hi) {
    asm("mov.b64 {%0, %1}, %2;" : "=f"(lo), "=f"(hi) : "l"(v));
}
__device__ __forceinline__ unsigned long long fma_x2(unsigned long long a,
                                                     unsigned long long b,
                                                     unsigned long long c) {
    unsigned long long d;
    asm("fma.rn.f32x2 %0, %1, %2, %3;" : "=l"(d) : "l"(a), "l"(b), "l"(c));
    return d;
}
__device__ __forceinline__ unsigned cvt_tf32(float f) {
    unsigned u;
    asm("cvt.rna.tf32.f32 %0, %1;" : "=r"(u) : "f"(f));
    return u;
}

extern __shared__ unsigned dsm[];

// ============================================================================
// Phase 1 detector (tensor-core): spikes pinned to 0 => linear system.
// cur chunk via mma.sync tf32, then per-neuron IIR scan. Sound with margin:
// approx error ~1e-2 vs margins (1.0 - 0.75) and (0.75 - ~0.4).
// ============================================================================
__global__ void __launch_bounds__(DTHR, 2)
snn_detect_tc(const float* __restrict__ x,
              const float* __restrict__ W1,
              const float* __restrict__ b1,
              const float* __restrict__ tau_n,
              const float* __restrict__ tau_m1,
              const float* __restrict__ mask)
{
    unsigned* Ws  = dsm;                    // [200][36] tf32 bits
    unsigned* xs  = dsm + SM_WS;            // [2][64][36] tf32 bits
    float*    cur = (float*)(dsm + SM_WS + SM_XS);   // [64][200]

    const int tid  = threadIdx.x;
    const int wid  = tid >> 5;
    const int lane = tid & 31;
    const int g    = lane >> 2;     // groupID
    const int tg   = lane & 3;      // threadID_in_group
    const int b    = blockIdx.x;

    if (tid == 0) g_flags[b] = 0;

    // stage masked W as tf32 (coalesced)
    for (int idx = tid; idx < N_HID * N_INP; idx += DTHR) {
        int nn = idx >> 5, kk = idx & 31;
        Ws[nn * WPAD + kk] = cvt_tf32(W1[nn * KDIM + kk] * mask[nn * KDIM + kk]);
    }

    // per-neuron scan params
    float beta = 0.f, omb = 0.f, ombB = 0.f, a1 = 0.f, oma1 = 0.f;
    if (tid < N_HID) {
        beta = sigm(tau_n[tid]);  omb  = 1.0f - beta;  ombB = omb * b1[tid];
        a1   = sigm(tau_m1[tid]); oma1 = 1.0f - a1;
    }

    // warp work split: 2 M-tiles per warp, nt ranges {0-6,7-12,13-18,19-24}
    const int mt0 = (wid & 1) * 2;
    const int q   = wid >> 1;
    const int ntS = (q == 0) ? 0 : 7 + 6 * (q - 1);
    const int ntE = ntS + ((q == 0) ? 7 : 6);

    const float4* xg = (const float4*)(x + (size_t)b * T_STEPS * N_INP);

    // prologue: stage chunk 0
    for (int u = 0; u < 2; ++u) {
        int f = tid + u * DTHR;               // 0..511
        int tl = f >> 3, i4 = f & 7;
        float4 v = (tl < T_STEPS) ? xg[(size_t)tl * 8 + i4] : make_float4(0,0,0,0);
        uint4 w4 = make_uint4(cvt_tf32(v.x), cvt_tf32(v.y), cvt_tf32(v.z), cvt_tf32(v.w));
        *(uint4*)&xs[tl * XPAD + i4 * 4] = w4;
    }
    __syncthreads();

    float din = 0.f, mem = 0.f, mmax = 0.f;

#pragma unroll 1
    for (int c = 0; c < NCH; ++c) {
        // prefetch next chunk's x (held in regs across the GEMM)
        float4 p[2];
        const bool more = (c + 1) < NCH;
        if (more) {
#pragma unroll
            for (int u = 0; u < 2; ++u) {
                int f = tid + u * DTHR;
                int t = (c + 1) * TC + (f >> 3);
                p[u] = (t < T_STEPS) ? xg[(size_t)t * 8 + (f & 7)]
                                     : make_float4(0,0,0,0);
            }
        }

        // ---- GEMM: cur[64 t][200 n] = x_chunk @ W^T (tf32 mma) ----
        {
            const unsigned* xb = xs + (c & 1) * (TC * XPAD);
            unsigned ua[2][4][4];
#pragma unroll
            for (int m2 = 0; m2 < 2; ++m2) {
                int r0 = (mt0 + m2) * 16 + g;
#pragma unroll
                for (int ks = 0; ks < 4; ++ks) {
                    int col = ks * 8 + tg;
                    ua[m2][ks][0] = xb[r0 * XPAD + col];
                    ua[m2][ks][1] = xb[(r0 + 8) * XPAD + col];
                    ua[m2][ks][2] = xb[r0 * XPAD + col + 4];
                    ua[m2][ks][3] = xb[(r0 + 8) * XPAD + col + 4];
                }
            }
#pragma unroll 1
            for (int nt = ntS; nt < ntE; ++nt) {
                unsigned ub[4][2];
#pragma unroll
                for (int ks = 0; ks < 4; ++ks) {
                    ub[ks][0] = Ws[(nt * 8 + g) * WPAD + ks * 8 + tg];
                    ub[ks][1] = Ws[(nt * 8 + g) * WPAD + ks * 8 + tg + 4];
                }
#pragma unroll
                for (int m2 = 0; m2 < 2; ++m2) {
                    float c0 = 0.f, c1 = 0.f, c2 = 0.f, c3 = 0.f;
#pragma unroll
                    for (int ks = 0; ks < 4; ++ks)
                        asm volatile(
                            "mma.sync.aligned.m16n8k8.row.col.f32.tf32.tf32.f32 "
                            "{%0,%1,%2,%3}, {%4,%5,%6,%7}, {%8,%9}, {%0,%1,%2,%3};"
                            : "+f"(c0), "+f"(c1), "+f"(c2), "+f"(c3)
                            : "r"(ua[m2][ks][0]), "r"(ua[m2][ks][1]),
                              "r"(ua[m2][ks][2]), "r"(ua[m2][ks][3]),
                              "r"(ub[ks][0]), "r"(ub[ks][1]));
                    int r0 = (mt0 + m2) * 16 + g;
                    int cc = nt * 8 + 2 * tg;
                    *(float2*)&cur[r0 * N_HID + cc]       = make_float2(c0, c1);
                    *(float2*)&cur[(r0 + 8) * N_HID + cc] = make_float2(c2, c3);
                }
            }
        }

        // stage prefetched x into the other buffer
        if (more) {
            unsigned* xbN = xs + ((c + 1) & 1) * (TC * XPAD);
#pragma unroll
            for (int u = 0; u < 2; ++u) {
                int f = tid + u * DTHR;
                int tl = f >> 3, i4 = f & 7;
                uint4 w4 = make_uint4(cvt_tf32(p[u].x), cvt_tf32(p[u].y),
                                      cvt_tf32(p[u].z), cvt_tf32(p[u].w));
                *(uint4*)&xbN[tl * XPAD + i4 * 4] = w4;
            }
        }
        __syncthreads();   // cur ready; next x buffer ready

        // ---- scan: 2 cascaded first-order IIRs per neuron ----
        if (tid < N_HID) {
#pragma unroll 8
            for (int s = 0; s < TC; ++s) {
                float cv = cur[s * N_HID + tid];
                din  = fmaf(beta, din, fmaf(omb, cv, ombB));
                mem  = fmaf(a1, mem, oma1 * din);
                mmax = fmaxf(mmax, mem);
            }
        }
        __syncthreads();   // scan done before cur is overwritten
    }

    if (tid < N_HID && mmax > DET_TH) atomicOr(&g_flags[b], 1u);
}

// ============================================================================
// Phase 2: flags==0 -> closed-form output (bit-identical zero-spike epilogue).
// flags!=0 -> full exact synchronized recurrence (fallback, never expected).
// ============================================================================
#define XG(bl, T) __ldg(xbase + (size_t)(bl) * (T_STEPS * N_INP) + (size_t)(T) * N_INP)

__global__ void __launch_bounds__(NTHR, 1)
snn_solve_kernel(const float* __restrict__ x,
                 const float* __restrict__ W1,
                 const float* __restrict__ b1,
                 const float* __restrict__ tau_n,
                 const float* __restrict__ tau_m1,
                 const float* __restrict__ W2,
                 const float* __restrict__ b2,
                 const float* __restrict__ tau_m2,
                 const float* __restrict__ mask,
                 float* __restrict__ out)
{
    __shared__ float4   xs4[4 * N_INP];
    __shared__ unsigned summ[3 * 4];
    __shared__ unsigned msk[3 * 7 * 4];
    __shared__ float    red[N_OUT * NB * N_HID];

    const int tid  = threadIdx.x;
    const int wid  = tid >> 5;
    const int lane = tid & 31;
    const int b0   = blockIdx.x * NB;

    float a2v[N_OUT];
#pragma unroll
    for (int o = 0; o < N_OUT; ++o) a2v[o] = sigm(tau_m2[o]);

    unsigned fl = g_flags[4 * blockIdx.x]     | g_flags[4 * blockIdx.x + 1] |
                  g_flags[4 * blockIdx.x + 2] | g_flags[4 * blockIdx.x + 3];
    if (fl == 0u) {
        if (tid < N_OUT * NB) {
            const int o = tid / NB;
            const int b = tid % NB;
            const float a   = a2v[o];
            const float aT  = powf(a, (float)T_STEPS);
            const float amT = a - aT;
            const float Sc  = amT + (float)(T_STEPS - 1) - amT / (1.0f - a);
            out[(size_t)(b0 + b) * N_OUT + o] = (0.0f + b2[o] * Sc) * (1.0f / (float)T_STEPS);
        }
        return;
    }

    // ---------------- exact fallback (never expected to execute) -------------
    if (tid < 12) summ[tid] = 0;

    const int  n       = tid;
    const bool active  = (n < N_HID);
    const bool is_comp = (wid < 7);

    float beta = 0.f, omb = 0.f, a1 = 0.f, oma1 = 0.f;
    unsigned long long wpk[N_INP];
    unsigned long long b1pk = 0ull;
    if (active) {
        beta = sigm(tau_n[n]);   omb  = 1.0f - beta;
        a1   = sigm(tau_m1[n]);  oma1 = 1.0f - a1;
        b1pk = pack_dup(b1[n]);
#pragma unroll
        for (int i = 0; i < N_INP; ++i)
            wpk[i] = pack_dup(W1[n * KDIM + i] * mask[n * KDIM + i]);
    } else {
#pragma unroll
        for (int i = 0; i < N_INP; ++i) wpk[i] = 0ull;
    }

    float mem1[NB] = {0.f,0.f,0.f,0.f};
    float din [NB] = {0.f,0.f,0.f,0.f};
    float spk [NB] = {0.f,0.f,0.f,0.f};
    float Us  [NB] = {0.f,0.f,0.f,0.f};
    float spk0[NB] = {0.f,0.f,0.f,0.f};
    float Wac[N_OUT][NB];
#pragma unroll
    for (int o = 0; o < N_OUT; ++o)
#pragma unroll
        for (int b = 0; b < NB; ++b) Wac[o][b] = 0.f;

    const float* xbase = x + (size_t)b0 * (T_STEPS * N_INP) + lane;
    float4 rC = make_float4(0.f,0.f,0.f,0.f), rD = rC;
    if (wid == 7) {
        float4 A, Bv;
        A.x  = XG(0,0); A.y  = XG(1,0); A.z  = XG(2,0); A.w  = XG(3,0);
        Bv.x = XG(0,1); Bv.y = XG(1,1); Bv.z = XG(2,1); Bv.w = XG(3,1);
        rC.x = XG(0,2); rC.y = XG(1,2); rC.z = XG(2,2); rC.w = XG(3,2);
        rD.x = XG(0,3); rD.y = XG(1,3); rD.z = XG(2,3); rD.w = XG(3,3);
        xs4[0 * N_INP + lane] = A;
        xs4[1 * N_INP + lane] = Bv;
    }
    __syncthreads();

    int pw = 0;
#pragma unroll 1
    for (int t = 0; t < T_STEPS; ++t) {
        int pz = pw + 1; if (pz == 3) pz = 0;
        int pr = pz + 1; if (pr == 3) pr = 0;

        if (is_comp) {
            unsigned long long acc01 = b1pk, acc23 = b1pk;
            const ulonglong2* xv = (const ulonglong2*)(xs4 + (t & 3) * N_INP);
#pragma unroll
            for (int i = 0; i < N_INP; ++i) {
                ulonglong2 kv = xv[i];
                acc01 = fma_x2(wpk[i], kv.x, acc01);
                acc23 = fma_x2(wpk[i], kv.y, acc23);
            }
            float cv[NB];
            unpack2(acc01, cv[0], cv[1]);
            unpack2(acc23, cv[2], cv[3]);

            uint4 sv = *(const uint4*)(summ + pr * 4);
            if (sv.x | sv.y | sv.z | sv.w) {
#pragma unroll
                for (int b = 0; b < NB; ++b) {
                    unsigned sb = (b == 0) ? sv.x : (b == 1) ? sv.y : (b == 2) ? sv.z : sv.w;
                    if (sb) {
#pragma unroll 1
                        for (int w = 0; w < 7; ++w) {
                            unsigned m = msk[(pr * 7 + w) * 4 + b];
                            while (m) {
                                int j = (w << 5) + __ffs(m) - 1;
                                m &= m - 1;
                                if (active)
                                    cv[b] += W1[n * KDIM + N_INP + j] *
                                             mask[n * KDIM + N_INP + j];
                            }
                        }
                    }
                }
            }

#pragma unroll
            for (int b = 0; b < NB; ++b) {
                din[b]  = fmaf(beta, din[b], omb * cv[b]);
                mem1[b] = fmaf(a1, mem1[b], oma1 * din[b]) - spk[b];
                spk[b]  = (mem1[b] > VTH) ? 1.0f : 0.0f;
            }

            unsigned bal0 = __ballot_sync(0xffffffffu, spk[0] > 0.f);
            unsigned bal1 = __ballot_sync(0xffffffffu, spk[1] > 0.f);
            unsigned bal2 = __ballot_sync(0xffffffffu, spk[2] > 0.f);
            unsigned bal3 = __ballot_sync(0xffffffffu, spk[3] > 0.f);
            if (lane < 4) {
                unsigned mw = (lane == 0) ? bal0 : (lane == 1) ? bal1
                            : (lane == 2) ? bal2 : bal3;
                msk[(pw * 7 + wid) * 4 + lane] = mw;
                if (mw) atomicOr(&summ[pw * 4 + lane], mw);
            }
            if (tid < 4) summ[pz * 4 + tid] = 0;

            if (t == 0) {
#pragma unroll
                for (int b = 0; b < NB; ++b) spk0[b] = spk[b];
            } else {
#pragma unroll
                for (int b = 0; b < NB; ++b) Us[b] += spk[b];
            }
#pragma unroll
            for (int o = 0; o < N_OUT; ++o)
#pragma unroll
                for (int b = 0; b < NB; ++b)
                    Wac[o][b] = fmaf(a2v[o], Wac[o][b], spk[b]);
        } else {
            int tp2 = t + 2, tp4 = t + 4;
            if ((t & 1) == 0) {
                if (tp2 < T_STEPS) xs4[(tp2 & 3) * N_INP + lane] = rC;
                if (tp4 < T_STEPS) {
                    rC.x = XG(0,tp4); rC.y = XG(1,tp4);
                    rC.z = XG(2,tp4); rC.w = XG(3,tp4);
                }
            } else {
                if (tp2 < T_STEPS) xs4[(tp2 & 3) * N_INP + lane] = rD;
                if (tp4 < T_STEPS) {
                    rD.x = XG(0,tp4); rD.y = XG(1,tp4);
                    rD.z = XG(2,tp4); rD.w = XG(3,tp4);
                }
            }
        }
        __syncthreads();
        pw = pz;
    }

    if (active) {
#pragma unroll
        for (int o = 0; o < N_OUT; ++o)
#pragma unroll
            for (int b = 0; b < NB; ++b)
                red[(o * NB + b) * N_HID + n] = Us[b] + a2v[o] * (spk0[b] - Wac[o][b]);
    }
    __syncthreads();

    if (tid < N_OUT * NB) {
        const int o = tid / NB;
        const int b = tid % NB;
        const float* Arow = red + tid * N_HID;
        const float* w2r  = W2 + o * N_HID;
        float s = 0.f;
#pragma unroll 8
        for (int j = 0; j < N_HID; ++j) s = fmaf(__ldg(w2r + j), Arow[j], s);

        const float a   = a2v[o];
        const float aT  = powf(a, (float)T_STEPS);
        const float amT = a - aT;
        const float Sc  = amT + (float)(T_STEPS - 1) - amT / (1.0f - a);

        out[(size_t)(b0 + b) * N_OUT + o] = (s + b2[o] * Sc) * (1.0f / (float)T_STEPS);
    }
}

extern "C" void kernel_launch(void* const* d_in, const int* in_sizes, int n_in,
                              void* d_out, int out_size) {
    const float* x      = (const float*)d_in[0];
    const float* W1     = (const float*)d_in[1];
    const float* b1     = (const float*)d_in[2];
    const float* tau_n  = (const float*)d_in[3];
    const float* tau_m1 = (const float*)d_in[4];
    const float* W2     = (const float*)d_in[5];
    const float* b2     = (const float*)d_in[6];
    const float* tau_m2 = (const float*)d_in[7];
    const float* mask   = (const float*)d_in[8];
    float*       out    = (float*)d_out;

    cudaFuncSetAttribute(snn_detect_tc,
                         cudaFuncAttributeMaxDynamicSharedMemorySize, DET_SMEM_BYTES);

    snn_detect_tc<<<B_TOT, DTHR, DET_SMEM_BYTES>>>(x, W1, b1, tau_n, tau_m1, mask);
    snn_solve_kernel<<<SCTA, NTHR>>>(x, W1, b1, tau_n, tau_m1, W2, b2, tau_m2, mask, out);
}

// round 16
// speedup vs baseline: 8.3451x; 1.3489x over previous
#include <cuda_runtime.h>
#include <math.h>

#define B_TOT   512
#define T_STEPS 2000
#define N_INP   32
#define N_HID   200
#define N_OUT   3
#define KDIM    (N_INP + N_HID)
#define VTH     1.0f
#define DET_TH  0.75f

// ---- detect kernel: 512 CTAs (1 batch each), bf16 MMA + overlapped scan ----
#define DTHR    256
#define TC      32
#define NCH     63                 // 63*32 = 2016 >= 2000 (zero-padded tail)
#define WROW    40                 // halves per W row (20 words -> conflict-free frags)
#define XROW    40

#define SM_W_BYTES   (N_HID * WROW * 2)        // 16000
#define SM_X_BYTES   (2 * TC * XROW * 2)       // 5120
#define SM_CUR_BYTES (2 * TC * N_HID * 4)      // 51200
#define DET_SMEM_BYTES (SM_W_BYTES + SM_X_BYTES + SM_CUR_BYTES)   // 72320

// ---- solve kernel config (proven R15 path) ----
#define NB      4
#define SCTA    (B_TOT / NB)
#define NTHR    256

__device__ unsigned g_flags[B_TOT];

__device__ __forceinline__ float sigm(float v) { return 1.0f / (1.0f + expf(-v)); }

__device__ __forceinline__ unsigned long long pack_dup(float w) {
    unsigned long long r;
    asm("mov.b64 %0, {%1, %1};" : "=l"(r) : "f"(w));
    return r;
}
__device__ __forceinline__ unsigned long long pack2(float lo, float hi) {
    unsigned long long r;
    asm("mov.b64 %0, {%1, %2};" : "=l"(r) : "f"(lo), "f"(hi));
    return r;
}
__device__ __forceinline__ void unpack2(unsigned long long v, float& lo, float& hi) {
    asm("mov.b64 {%0, %1}, %2;" : "=f"(lo), "=f"(hi) : "l"(v));
}
__device__ __forceinline__ unsigned long long fma_x2(unsigned long long a,
                                                     unsigned long long b,
                                                     unsigned long long c) {
    unsigned long long d;
    asm("fma.rn.f32x2 %0, %1, %2, %3;" : "=l"(d) : "l"(a), "l"(b), "l"(c));
    return d;
}
__device__ __forceinline__ unsigned long long mul_x2(unsigned long long a,
                                                     unsigned long long b) {
    unsigned long long d;
    asm("mul.rn.f32x2 %0, %1, %2;" : "=l"(d) : "l"(a), "l"(b));
    return d;
}
__device__ __forceinline__ unsigned short f2bf(float f) {
    unsigned short h;
    asm("cvt.rn.bf16.f32 %0, %1;" : "=h"(h) : "f"(f));
    return h;
}
__device__ __forceinline__ unsigned f2bf2(float lo, float hi) {
    unsigned r;   // lower 16 bits = lo (first element in memory/K order)
    asm("cvt.rn.bf16x2.f32 %0, %1, %2;" : "=r"(r) : "f"(hi), "f"(lo));
    return r;
}

extern __shared__ char dsm8[];

// ============================================================================
// Phase 1 detector: spikes pinned to 0 => linear system. Warp-specialized:
// warps 0-3 GEMM (bf16 mma m16n8k16) + x staging; warps 4-7 scan previous
// chunk's cur via packed f32x2 IIRs. Double-buffered cur, 1 barrier/chunk.
// ============================================================================
__global__ void __launch_bounds__(DTHR, 2)
snn_detect_tc(const float* __restrict__ x,
              const float* __restrict__ W1,
              const float* __restrict__ b1,
              const float* __restrict__ tau_n,
              const float* __restrict__ tau_m1,
              const float* __restrict__ mask)
{
    unsigned short* Wh  = (unsigned short*)dsm8;                       // [200][40]
    unsigned short* Xh  = (unsigned short*)(dsm8 + SM_W_BYTES);        // [2][32][40]
    float*          cur = (float*)(dsm8 + SM_W_BYTES + SM_X_BYTES);    // [2][32][200]
    const unsigned* Ww  = (const unsigned*)Wh;   // word view, row stride 20
    const unsigned* Xw  = (const unsigned*)Xh;   // word view, buf stride 640

    const int tid  = threadIdx.x;
    const int wid  = tid >> 5;
    const int lane = tid & 31;
    const int g    = lane >> 2;
    const int tg   = lane & 3;
    const int b    = blockIdx.x;

    if (tid == 0) g_flags[b] = 0;

    // stage masked W as bf16
    for (int idx = tid; idx < N_HID * N_INP; idx += DTHR) {
        int nn = idx >> 5, kk = idx & 31;
        Wh[nn * WROW + kk] = f2bf(W1[nn * KDIM + kk] * mask[nn * KDIM + kk]);
    }

    const float4* xg = (const float4*)(x + (size_t)b * T_STEPS * N_INP);

    // ---- scan-warp parameters: 2 neurons per thread, packed f32x2 ----
    const int  u      = tid - 128;            // scan index, warps 4-7
    const bool s_act  = (wid >= 4) && (u < 100);
    unsigned long long pB = 0, pOmb = 0, pOmbB = 0, pA1 = 0, pOma1 = 0;
    if (s_act) {
        int n0 = 2 * u;
        float be0 = sigm(tau_n[n0]),     be1 = sigm(tau_n[n0 + 1]);
        float a10 = sigm(tau_m1[n0]),    a11 = sigm(tau_m1[n0 + 1]);
        pB    = pack2(be0, be1);
        pOmb  = pack2(1.0f - be0, 1.0f - be1);
        pOmbB = pack2((1.0f - be0) * b1[n0], (1.0f - be1) * b1[n0 + 1]);
        pA1   = pack2(a10, a11);
        pOma1 = pack2(1.0f - a10, 1.0f - a11);
    }

    // ---- prologue: stage x chunk 0 into buffer 0 (threads 0-127) ----
    if (tid < 128) {
#pragma unroll
        for (int q = 0; q < 2; ++q) {
            int f  = tid + q * 128;            // float4 index in chunk (0..255)
            int tl = f >> 3, i4 = f & 7;
            float4 v = (tl < T_STEPS) ? xg[(size_t)tl * 8 + i4]
                                      : make_float4(0, 0, 0, 0);
            *(uint2*)&Xh[tl * XROW + i4 * 4] =
                make_uint2(f2bf2(v.x, v.y), f2bf2(v.z, v.w));
        }
    }
    __syncthreads();

    unsigned long long din = 0ull, mem = 0ull;
    float mmax0 = 0.f, mmax1 = 0.f;

#pragma unroll 1
    for (int c = 0; c < NCH; ++c) {
        if (wid < 4) {
            // prefetch x for chunk c+1 (held in regs across the GEMM)
            float4 p0 = make_float4(0,0,0,0), p1 = p0;
            const bool more = (c + 1) < NCH;
            if (more) {
                int f0 = tid, f1 = tid + 128;
                int t0 = (c + 1) * TC + (f0 >> 3);
                int t1 = (c + 1) * TC + (f1 >> 3);
                if (t0 < T_STEPS) p0 = xg[(size_t)t0 * 8 + (f0 & 7)];
                if (t1 < T_STEPS) p1 = xg[(size_t)t1 * 8 + (f1 & 7)];
            }

            // ---- GEMM: cur[buf c&1][32 t][200 n] = x_chunk @ W^T (bf16 mma) ----
            const unsigned* xb = Xw + (c & 1) * 640;
            float*          cb = cur + (c & 1) * (TC * N_HID);
            unsigned ua[2][2][4];
#pragma unroll
            for (int m2 = 0; m2 < 2; ++m2) {
                int r0 = m2 * 16 + g;
#pragma unroll
                for (int ks = 0; ks < 2; ++ks) {
                    int base = tg + 8 * ks;
                    ua[m2][ks][0] = xb[r0 * 20 + base];
                    ua[m2][ks][1] = xb[(r0 + 8) * 20 + base];
                    ua[m2][ks][2] = xb[r0 * 20 + base + 4];
                    ua[m2][ks][3] = xb[(r0 + 8) * 20 + base + 4];
                }
            }
#pragma unroll 1
            for (int nt = wid; nt < 25; nt += 4) {
                unsigned ub[2][2];
#pragma unroll
                for (int ks = 0; ks < 2; ++ks) {
                    ub[ks][0] = Ww[(nt * 8 + g) * 20 + tg + 8 * ks];
                    ub[ks][1] = Ww[(nt * 8 + g) * 20 + tg + 8 * ks + 4];
                }
#pragma unroll
                for (int m2 = 0; m2 < 2; ++m2) {
                    float c0 = 0.f, c1 = 0.f, c2 = 0.f, c3 = 0.f;
#pragma unroll
                    for (int ks = 0; ks < 2; ++ks)
                        asm volatile(
                            "mma.sync.aligned.m16n8k16.row.col.f32.bf16.bf16.f32 "
                            "{%0,%1,%2,%3}, {%4,%5,%6,%7}, {%8,%9}, {%0,%1,%2,%3};"
                            : "+f"(c0), "+f"(c1), "+f"(c2), "+f"(c3)
                            : "r"(ua[m2][ks][0]), "r"(ua[m2][ks][1]),
                              "r"(ua[m2][ks][2]), "r"(ua[m2][ks][3]),
                              "r"(ub[ks][0]), "r"(ub[ks][1]));
                    int r0 = m2 * 16 + g;
                    int cc = nt * 8 + 2 * tg;
                    *(float2*)&cb[r0 * N_HID + cc]       = make_float2(c0, c1);
                    *(float2*)&cb[(r0 + 8) * N_HID + cc] = make_float2(c2, c3);
                }
            }

            // store staged x into the other buffer
            if (more) {
                unsigned short* xn = Xh + ((c + 1) & 1) * (TC * XROW);
                int f0 = tid, f1 = tid + 128;
                *(uint2*)&xn[(f0 >> 3) * XROW + (f0 & 7) * 4] =
                    make_uint2(f2bf2(p0.x, p0.y), f2bf2(p0.z, p0.w));
                *(uint2*)&xn[(f1 >> 3) * XROW + (f1 & 7) * 4] =
                    make_uint2(f2bf2(p1.x, p1.y), f2bf2(p1.z, p1.w));
            }
        } else if (s_act && c > 0) {
            // ---- scan chunk c-1 from the other cur buffer ----
            const float* cb = cur + ((c - 1) & 1) * (TC * N_HID) + 2 * u;
#pragma unroll 8
            for (int s = 0; s < TC; ++s) {
                float2 cv = *(const float2*)(cb + s * N_HID);
                unsigned long long cvp = pack2(cv.x, cv.y);
                din = fma_x2(pB, din, fma_x2(pOmb, cvp, pOmbB));
                mem = fma_x2(pA1, mem, mul_x2(pOma1, din));
                float m0, m1;
                unpack2(mem, m0, m1);
                mmax0 = fmaxf(mmax0, m0);
                mmax1 = fmaxf(mmax1, m1);
            }
        }
        __syncthreads();
    }

    // epilogue: scan last chunk (62 -> buffer 0)
    if (s_act) {
        const float* cb = cur + ((NCH - 1) & 1) * (TC * N_HID) + 2 * u;
#pragma unroll 8
        for (int s = 0; s < TC; ++s) {
            float2 cv = *(const float2*)(cb + s * N_HID);
            unsigned long long cvp = pack2(cv.x, cv.y);
            din = fma_x2(pB, din, fma_x2(pOmb, cvp, pOmbB));
            mem = fma_x2(pA1, mem, mul_x2(pOma1, din));
            float m0, m1;
            unpack2(mem, m0, m1);
            mmax0 = fmaxf(mmax0, m0);
            mmax1 = fmaxf(mmax1, m1);
        }
    }

    if (wid >= 4) {
        bool hit = s_act && (fmaxf(mmax0, mmax1) > DET_TH);
        unsigned bal = __ballot_sync(0xffffffffu, hit);
        if (lane == 0 && bal) atomicOr(&g_flags[b], 1u);
    }
}

// ============================================================================
// Phase 2: flags==0 -> closed-form output (bit-identical zero-spike epilogue).
// flags!=0 -> full exact synchronized recurrence (fallback, never expected).
// ============================================================================
#define XG(bl, T) __ldg(xbase + (size_t)(bl) * (T_STEPS * N_INP) + (size_t)(T) * N_INP)

__global__ void __launch_bounds__(NTHR, 1)
snn_solve_kernel(const float* __restrict__ x,
                 const float* __restrict__ W1,
                 const float* __restrict__ b1,
                 const float* __restrict__ tau_n,
                 const float* __restrict__ tau_m1,
                 const float* __restrict__ W2,
                 const float* __restrict__ b2,
                 const float* __restrict__ tau_m2,
                 const float* __restrict__ mask,
                 float* __restrict__ out)
{
    __shared__ float4   xs4[4 * N_INP];
    __shared__ unsigned summ[3 * 4];
    __shared__ unsigned msk[3 * 7 * 4];
    __shared__ float    red[N_OUT * NB * N_HID];

    const int tid  = threadIdx.x;
    const int wid  = tid >> 5;
    const int lane = tid & 31;
    const int b0   = blockIdx.x * NB;

    float a2v[N_OUT];
#pragma unroll
    for (int o = 0; o < N_OUT; ++o) a2v[o] = sigm(tau_m2[o]);

    unsigned fl = g_flags[4 * blockIdx.x]     | g_flags[4 * blockIdx.x + 1] |
                  g_flags[4 * blockIdx.x + 2] | g_flags[4 * blockIdx.x + 3];
    if (fl == 0u) {
        if (tid < N_OUT * NB) {
            const int o = tid / NB;
            const int b = tid % NB;
            const float a   = a2v[o];
            const float aT  = powf(a, (float)T_STEPS);
            const float amT = a - aT;
            const float Sc  = amT + (float)(T_STEPS - 1) - amT / (1.0f - a);
            out[(size_t)(b0 + b) * N_OUT + o] = (0.0f + b2[o] * Sc) * (1.0f / (float)T_STEPS);
        }
        return;
    }

    // ---------------- exact fallback (never expected to execute) -------------
    if (tid < 12) summ[tid] = 0;

    const int  n       = tid;
    const bool active  = (n < N_HID);
    const bool is_comp = (wid < 7);

    float beta = 0.f, omb = 0.f, a1 = 0.f, oma1 = 0.f;
    unsigned long long wpk[N_INP];
    unsigned long long b1pk = 0ull;
    if (active) {
        beta = sigm(tau_n[n]);   omb  = 1.0f - beta;
        a1   = sigm(tau_m1[n]);  oma1 = 1.0f - a1;
        b1pk = pack_dup(b1[n]);
#pragma unroll
        for (int i = 0; i < N_INP; ++i)
            wpk[i] = pack_dup(W1[n * KDIM + i] * mask[n * KDIM + i]);
    } else {
#pragma unroll
        for (int i = 0; i < N_INP; ++i) wpk[i] = 0ull;
    }

    float mem1[NB] = {0.f,0.f,0.f,0.f};
    float din [NB] = {0.f,0.f,0.f,0.f};
    float spk [NB] = {0.f,0.f,0.f,0.f};
    float Us  [NB] = {0.f,0.f,0.f,0.f};
    float spk0[NB] = {0.f,0.f,0.f,0.f};
    float Wac[N_OUT][NB];
#pragma unroll
    for (int o = 0; o < N_OUT; ++o)
#pragma unroll
        for (int b = 0; b < NB; ++b) Wac[o][b] = 0.f;

    const float* xbase = x + (size_t)b0 * (T_STEPS * N_INP) + lane;
    float4 rC = make_float4(0.f,0.f,0.f,0.f), rD = rC;
    if (wid == 7) {
        float4 A, Bv;
        A.x  = XG(0,0); A.y  = XG(1,0); A.z  = XG(2,0); A.w  = XG(3,0);
        Bv.x = XG(0,1); Bv.y = XG(1,1); Bv.z = XG(2,1); Bv.w = XG(3,1);
        rC.x = XG(0,2); rC.y = XG(1,2); rC.z = XG(2,2); rC.w = XG(3,2);
        rD.x = XG(0,3); rD.y = XG(1,3); rD.z = XG(2,3); rD.w = XG(3,3);
        xs4[0 * N_INP + lane] = A;
        xs4[1 * N_INP + lane] = Bv;
    }
    __syncthreads();

    int pw = 0;
#pragma unroll 1
    for (int t = 0; t < T_STEPS; ++t) {
        int pz = pw + 1; if (pz == 3) pz = 0;
        int pr = pz + 1; if (pr == 3) pr = 0;

        if (is_comp) {
            unsigned long long acc01 = b1pk, acc23 = b1pk;
            const ulonglong2* xv = (const ulonglong2*)(xs4 + (t & 3) * N_INP);
#pragma unroll
            for (int i = 0; i < N_INP; ++i) {
                ulonglong2 kv = xv[i];
                acc01 = fma_x2(wpk[i], kv.x, acc01);
                acc23 = fma_x2(wpk[i], kv.y, acc23);
            }
            float cv[NB];
            unpack2(acc01, cv[0], cv[1]);
            unpack2(acc23, cv[2], cv[3]);

            uint4 sv = *(const uint4*)(summ + pr * 4);
            if (sv.x | sv.y | sv.z | sv.w) {
#pragma unroll
                for (int b = 0; b < NB; ++b) {
                    unsigned sb = (b == 0) ? sv.x : (b == 1) ? sv.y : (b == 2) ? sv.z : sv.w;
                    if (sb) {
#pragma unroll 1
                        for (int w = 0; w < 7; ++w) {
                            unsigned m = msk[(pr * 7 + w) * 4 + b];
                            while (m) {
                                int j = (w << 5) + __ffs(m) - 1;
                                m &= m - 1;
                                if (active)
                                    cv[b] += W1[n * KDIM + N_INP + j] *
                                             mask[n * KDIM + N_INP + j];
                            }
                        }
                    }
                }
            }

#pragma unroll
            for (int b = 0; b < NB; ++b) {
                din[b]  = fmaf(beta, din[b], omb * cv[b]);
                mem1[b] = fmaf(a1, mem1[b], oma1 * din[b]) - spk[b];
                spk[b]  = (mem1[b] > VTH) ? 1.0f : 0.0f;
            }

            unsigned bal0 = __ballot_sync(0xffffffffu, spk[0] > 0.f);
            unsigned bal1 = __ballot_sync(0xffffffffu, spk[1] > 0.f);
            unsigned bal2 = __ballot_sync(0xffffffffu, spk[2] > 0.f);
            unsigned bal3 = __ballot_sync(0xffffffffu, spk[3] > 0.f);
            if (lane < 4) {
                unsigned mw = (lane == 0) ? bal0 : (lane == 1) ? bal1
                            : (lane == 2) ? bal2 : bal3;
                msk[(pw * 7 + wid) * 4 + lane] = mw;
                if (mw) atomicOr(&summ[pw * 4 + lane], mw);
            }
            if (tid < 4) summ[pz * 4 + tid] = 0;

            if (t == 0) {
#pragma unroll
                for (int b = 0; b < NB; ++b) spk0[b] = spk[b];
            } else {
#pragma unroll
                for (int b = 0; b < NB; ++b) Us[b] += spk[b];
            }
#pragma unroll
            for (int o = 0; o < N_OUT; ++o)
#pragma unroll
                for (int b = 0; b < NB; ++b)
                    Wac[o][b] = fmaf(a2v[o], Wac[o][b], spk[b]);
        } else {
            int tp2 = t + 2, tp4 = t + 4;
            if ((t & 1) == 0) {
                if (tp2 < T_STEPS) xs4[(tp2 & 3) * N_INP + lane] = rC;
                if (tp4 < T_STEPS) {
                    rC.x = XG(0,tp4); rC.y = XG(1,tp4);
                    rC.z = XG(2,tp4); rC.w = XG(3,tp4);
                }
            } else {
                if (tp2 < T_STEPS) xs4[(tp2 & 3) * N_INP + lane] = rD;
                if (tp4 < T_STEPS) {
                    rD.x = XG(0,tp4); rD.y = XG(1,tp4);
                    rD.z = XG(2,tp4); rD.w = XG(3,tp4);
                }
            }
        }
        __syncthreads();
        pw = pz;
    }

    if (active) {
#pragma unroll
        for (int o = 0; o < N_OUT; ++o)
#pragma unroll
            for (int b = 0; b < NB; ++b)
                red[(o * NB + b) * N_HID + n] = Us[b] + a2v[o] * (spk0[b] - Wac[o][b]);
    }
    __syncthreads();

    if (tid < N_OUT * NB) {
        const int o = tid / NB;
        const int b = tid % NB;
        const float* Arow = red + tid * N_HID;
        const float* w2r  = W2 + o * N_HID;
        float s = 0.f;
#pragma unroll 8
        for (int j = 0; j < N_HID; ++j) s = fmaf(__ldg(w2r + j), Arow[j], s);

        const float a   = a2v[o];
        const float aT  = powf(a, (float)T_STEPS);
        const float amT = a - aT;
        const float Sc  = amT + (float)(T_STEPS - 1) - amT / (1.0f - a);

        out[(size_t)(b0 + b) * N_OUT + o] = (s + b2[o] * Sc) * (1.0f / (float)T_STEPS);
    }
}

extern "C" void kernel_launch(void* const* d_in, const int* in_sizes, int n_in,
                              void* d_out, int out_size) {
    const float* x      = (const float*)d_in[0];
    const float* W1     = (const float*)d_in[1];
    const float* b1     = (const float*)d_in[2];
    const float* tau_n  = (const float*)d_in[3];
    const float* tau_m1 = (const float*)d_in[4];
    const float* W2     = (const float*)d_in[5];
    const float* b2     = (const float*)d_in[6];
    const float* tau_m2 = (const float*)d_in[7];
    const float* mask   = (const float*)d_in[8];
    float*       out    = (float*)d_out;

    cudaFuncSetAttribute(snn_detect_tc,
                         cudaFuncAttributeMaxDynamicSharedMemorySize, DET_SMEM_BYTES);

    snn_detect_tc<<<B_TOT, DTHR, DET_SMEM_BYTES>>>(x, W1, b1, tau_n, tau_m1, mask);
    snn_solve_kernel<<<SCTA, NTHR>>>(x, W1, b1, tau_n, tau_m1, W2, b2, tau_m2, mask, out);
}

// round 17
// speedup vs baseline: 10.6507x; 1.2763x over previous
#include <cuda_runtime.h>
#include <math.h>

#define B_TOT   512
#define T_STEPS 2000
#define N_INP   32
#define N_HID   200
#define N_OUT   3
#define KDIM    (N_INP + N_HID)
#define VTH     1.0f
#define DET_TH  0.75f

// ---- detect kernel: 512 CTAs (1 batch each), bf16 MMA + overlapped bf16 scan
#define DTHR    256
#define TC      32
#define NCH     63                 // 63*32 = 2016 >= 2000 (zero-padded tail)
#define WROW    40                 // halves per W row (20 words -> conflict-free frags)
#define XROW    40
#define CURW    (N_HID / 2)        // 100 bf16x2 words per cur row

#define SM_W_BYTES   (N_HID * WROW * 2)        // 16000
#define SM_X_BYTES   (2 * TC * XROW * 2)       // 5120
#define SM_CUR_BYTES (2 * TC * N_HID * 2)      // 25600 (bf16)
#define DET_SMEM_BYTES (SM_W_BYTES + SM_X_BYTES + SM_CUR_BYTES)   // 46720

// ---- solve kernel config (proven path) ----
#define NB      4
#define SCTA    (B_TOT / NB)
#define NTHR    256

__device__ unsigned g_flags[B_TOT];

__device__ __forceinline__ float sigm(float v) { return 1.0f / (1.0f + expf(-v)); }

__device__ __forceinline__ unsigned long long pack_dup(float w) {
    unsigned long long r;
    asm("mov.b64 %0, {%1, %1};" : "=l"(r) : "f"(w));
    return r;
}
__device__ __forceinline__ void unpack2(unsigned long long v, float& lo, float& hi) {
    asm("mov.b64 {%0, %1}, %2;" : "=f"(lo), "=f"(hi) : "l"(v));
}
__device__ __forceinline__ unsigned long long fma_x2(unsigned long long a,
                                                     unsigned long long b,
                                                     unsigned long long c) {
    unsigned long long d;
    asm("fma.rn.f32x2 %0, %1, %2, %3;" : "=l"(d) : "l"(a), "l"(b), "l"(c));
    return d;
}
__device__ __forceinline__ unsigned short f2bf(float f) {
    unsigned short h;
    asm("cvt.rn.bf16.f32 %0, %1;" : "=h"(h) : "f"(f));
    return h;
}
__device__ __forceinline__ unsigned f2bf2(float lo, float hi) {
    unsigned r;   // lower 16 bits = lo
    asm("cvt.rn.bf16x2.f32 %0, %1, %2;" : "=r"(r) : "f"(hi), "f"(lo));
    return r;
}
__device__ __forceinline__ unsigned bffma2(unsigned a, unsigned b, unsigned c) {
    unsigned d;
    asm("fma.rn.bf16x2 %0, %1, %2, %3;" : "=r"(d) : "r"(a), "r"(b), "r"(c));
    return d;
}
__device__ __forceinline__ unsigned bfmul2(unsigned a, unsigned b) {
    unsigned d;
    asm("mul.rn.bf16x2 %0, %1, %2;" : "=r"(d) : "r"(a), "r"(b));
    return d;
}
__device__ __forceinline__ unsigned bfmax2(unsigned a, unsigned b) {
    unsigned d;
    asm("max.bf16x2 %0, %1, %2;" : "=r"(d) : "r"(a), "r"(b));
    return d;
}
__device__ __forceinline__ float bf_lo(unsigned v) { return __uint_as_float(v << 16); }
__device__ __forceinline__ float bf_hi(unsigned v) { return __uint_as_float(v & 0xffff0000u); }

extern __shared__ char dsm8[];

// ============================================================================
// Phase 1 detector: spikes pinned to 0 => linear system. Warp-specialized:
// warps 0-3 GEMM (bf16 mma m16n8k16) + x staging; warps 4-7 scan previous
// chunk's cur (bf16x2 IIR, 2 neurons/thread). cur double-buffered in bf16
// => 46.7 KB SMEM => 4 CTAs/SM => single wave over 512 CTAs.
// ============================================================================
__global__ void __launch_bounds__(DTHR, 4)
snn_detect_tc(const float* __restrict__ x,
              const float* __restrict__ W1,
              const float* __restrict__ b1,
              const float* __restrict__ tau_n,
              const float* __restrict__ tau_m1,
              const float* __restrict__ mask)
{
    unsigned short* Wh  = (unsigned short*)dsm8;                      // [200][40]
    unsigned short* Xh  = (unsigned short*)(dsm8 + SM_W_BYTES);       // [2][32][40]
    unsigned*       cur = (unsigned*)(dsm8 + SM_W_BYTES + SM_X_BYTES);// [2][32][100] bf16x2
    const unsigned* Ww  = (const unsigned*)Wh;
    const unsigned* Xw  = (const unsigned*)Xh;

    const int tid  = threadIdx.x;
    const int wid  = tid >> 5;
    const int lane = tid & 31;
    const int g    = lane >> 2;
    const int tg   = lane & 3;
    const int b    = blockIdx.x;

    if (tid == 0) g_flags[b] = 0;

    // stage masked W as bf16
    for (int idx = tid; idx < N_HID * N_INP; idx += DTHR) {
        int nn = idx >> 5, kk = idx & 31;
        Wh[nn * WROW + kk] = f2bf(W1[nn * KDIM + kk] * mask[nn * KDIM + kk]);
    }

    const float4* xg = (const float4*)(x + (size_t)b * T_STEPS * N_INP);

    // ---- scan-warp parameters: 2 neurons per thread, bf16x2 packed ----
    const int  u     = tid - 128;
    const bool s_act = (wid >= 4) && (u < 100);
    unsigned pB = 0, pOmb = 0, pOmbB = 0, pA1 = 0, pOma1 = 0;
    if (s_act) {
        int n0 = 2 * u;
        float be0 = sigm(tau_n[n0]),  be1 = sigm(tau_n[n0 + 1]);
        float a10 = sigm(tau_m1[n0]), a11 = sigm(tau_m1[n0 + 1]);
        pB    = f2bf2(be0, be1);
        pOmb  = f2bf2(1.0f - be0, 1.0f - be1);
        pOmbB = f2bf2((1.0f - be0) * b1[n0], (1.0f - be1) * b1[n0 + 1]);
        pA1   = f2bf2(a10, a11);
        pOma1 = f2bf2(1.0f - a10, 1.0f - a11);
    }

    // ---- prologue: stage x chunk 0 into buffer 0 (threads 0-127) ----
    if (tid < 128) {
#pragma unroll
        for (int q = 0; q < 2; ++q) {
            int f  = tid + q * 128;
            int tl = f >> 3, i4 = f & 7;
            float4 v = (tl < T_STEPS) ? xg[(size_t)tl * 8 + i4]
                                      : make_float4(0, 0, 0, 0);
            *(uint2*)&Xh[tl * XROW + i4 * 4] =
                make_uint2(f2bf2(v.x, v.y), f2bf2(v.z, v.w));
        }
    }
    __syncthreads();

    unsigned din = 0u, mem = 0u, mmax = 0u;

#pragma unroll 1
    for (int c = 0; c < NCH; ++c) {
        if (wid < 4) {
            // prefetch x for chunk c+1 (held in regs across the GEMM)
            float4 p0 = make_float4(0,0,0,0), p1 = p0;
            const bool more = (c + 1) < NCH;
            if (more) {
                int f0 = tid, f1 = tid + 128;
                int t0 = (c + 1) * TC + (f0 >> 3);
                int t1 = (c + 1) * TC + (f1 >> 3);
                if (t0 < T_STEPS) p0 = xg[(size_t)t0 * 8 + (f0 & 7)];
                if (t1 < T_STEPS) p1 = xg[(size_t)t1 * 8 + (f1 & 7)];
            }

            // ---- GEMM: cur[buf][32 t][200 n] = x_chunk @ W^T (bf16 mma) ----
            const unsigned* xb = Xw + (c & 1) * 640;
            unsigned*       cb = cur + (c & 1) * (TC * CURW);
            unsigned ua[2][2][4];
#pragma unroll
            for (int m2 = 0; m2 < 2; ++m2) {
                int r0 = m2 * 16 + g;
#pragma unroll
                for (int ks = 0; ks < 2; ++ks) {
                    int base = tg + 8 * ks;
                    ua[m2][ks][0] = xb[r0 * 20 + base];
                    ua[m2][ks][1] = xb[(r0 + 8) * 20 + base];
                    ua[m2][ks][2] = xb[r0 * 20 + base + 4];
                    ua[m2][ks][3] = xb[(r0 + 8) * 20 + base + 4];
                }
            }
#pragma unroll 1
            for (int nt = wid; nt < 25; nt += 4) {
                unsigned ub[2][2];
#pragma unroll
                for (int ks = 0; ks < 2; ++ks) {
                    ub[ks][0] = Ww[(nt * 8 + g) * 20 + tg + 8 * ks];
                    ub[ks][1] = Ww[(nt * 8 + g) * 20 + tg + 8 * ks + 4];
                }
#pragma unroll
                for (int m2 = 0; m2 < 2; ++m2) {
                    float c0 = 0.f, c1 = 0.f, c2 = 0.f, c3 = 0.f;
#pragma unroll
                    for (int ks = 0; ks < 2; ++ks)
                        asm volatile(
                            "mma.sync.aligned.m16n8k16.row.col.f32.bf16.bf16.f32 "
                            "{%0,%1,%2,%3}, {%4,%5,%6,%7}, {%8,%9}, {%0,%1,%2,%3};"
                            : "+f"(c0), "+f"(c1), "+f"(c2), "+f"(c3)
                            : "r"(ua[m2][ks][0]), "r"(ua[m2][ks][1]),
                              "r"(ua[m2][ks][2]), "r"(ua[m2][ks][3]),
                              "r"(ub[ks][0]), "r"(ub[ks][1]));
                    int r0 = m2 * 16 + g;
                    int cw = nt * 4 + tg;             // bf16x2 word index in row
                    cb[r0 * CURW + cw]       = f2bf2(c0, c1);
                    cb[(r0 + 8) * CURW + cw] = f2bf2(c2, c3);
                }
            }

            // store staged x into the other buffer
            if (more) {
                unsigned short* xn = Xh + ((c + 1) & 1) * (TC * XROW);
                int f0 = tid, f1 = tid + 128;
                *(uint2*)&xn[(f0 >> 3) * XROW + (f0 & 7) * 4] =
                    make_uint2(f2bf2(p0.x, p0.y), f2bf2(p0.z, p0.w));
                *(uint2*)&xn[(f1 >> 3) * XROW + (f1 & 7) * 4] =
                    make_uint2(f2bf2(p1.x, p1.y), f2bf2(p1.z, p1.w));
            }
        } else if (s_act && c > 0) {
            // ---- scan chunk c-1 (bf16x2 IIR, 2 neurons/thread) ----
            const unsigned* cb = cur + ((c - 1) & 1) * (TC * CURW) + u;
#pragma unroll 8
            for (int s = 0; s < TC; ++s) {
                unsigned cv = cb[s * CURW];
                din  = bffma2(pB, din, bffma2(pOmb, cv, pOmbB));
                mem  = bffma2(pA1, mem, bfmul2(pOma1, din));
                mmax = bfmax2(mmax, mem);
            }
        }
        __syncthreads();
    }

    // epilogue: scan last chunk
    if (s_act) {
        const unsigned* cb = cur + ((NCH - 1) & 1) * (TC * CURW) + u;
#pragma unroll 8
        for (int s = 0; s < TC; ++s) {
            unsigned cv = cb[s * CURW];
            din  = bffma2(pB, din, bffma2(pOmb, cv, pOmbB));
            mem  = bffma2(pA1, mem, bfmul2(pOma1, din));
            mmax = bfmax2(mmax, mem);
        }
    }

    if (wid >= 4) {
        bool hit = s_act && (fmaxf(bf_lo(mmax), bf_hi(mmax)) > DET_TH);
        unsigned bal = __ballot_sync(0xffffffffu, hit);
        if (lane == 0 && bal) atomicOr(&g_flags[b], 1u);
    }
}

// ============================================================================
// Phase 2: flags==0 -> closed-form output (bit-identical zero-spike epilogue).
// flags!=0 -> full exact synchronized recurrence (fallback, never expected).
// ============================================================================
#define XG(bl, T) __ldg(xbase + (size_t)(bl) * (T_STEPS * N_INP) + (size_t)(T) * N_INP)

__global__ void __launch_bounds__(NTHR, 1)
snn_solve_kernel(const float* __restrict__ x,
                 const float* __restrict__ W1,
                 const float* __restrict__ b1,
                 const float* __restrict__ tau_n,
                 const float* __restrict__ tau_m1,
                 const float* __restrict__ W2,
                 const float* __restrict__ b2,
                 const float* __restrict__ tau_m2,
                 const float* __restrict__ mask,
                 float* __restrict__ out)
{
    __shared__ float4   xs4[4 * N_INP];
    __shared__ unsigned summ[3 * 4];
    __shared__ unsigned msk[3 * 7 * 4];
    __shared__ float    red[N_OUT * NB * N_HID];

    const int tid  = threadIdx.x;
    const int wid  = tid >> 5;
    const int lane = tid & 31;
    const int b0   = blockIdx.x * NB;

    float a2v[N_OUT];
#pragma unroll
    for (int o = 0; o < N_OUT; ++o) a2v[o] = sigm(tau_m2[o]);

    unsigned fl = g_flags[4 * blockIdx.x]     | g_flags[4 * blockIdx.x + 1] |
                  g_flags[4 * blockIdx.x + 2] | g_flags[4 * blockIdx.x + 3];
    if (fl == 0u) {
        if (tid < N_OUT * NB) {
            const int o = tid / NB;
            const int b = tid % NB;
            const float a   = a2v[o];
            const float aT  = powf(a, (float)T_STEPS);
            const float amT = a - aT;
            const float Sc  = amT + (float)(T_STEPS - 1) - amT / (1.0f - a);
            out[(size_t)(b0 + b) * N_OUT + o] = (0.0f + b2[o] * Sc) * (1.0f / (float)T_STEPS);
        }
        return;
    }

    // ---------------- exact fallback (never expected to execute) -------------
    if (tid < 12) summ[tid] = 0;

    const int  n       = tid;
    const bool active  = (n < N_HID);
    const bool is_comp = (wid < 7);

    float beta = 0.f, omb = 0.f, a1 = 0.f, oma1 = 0.f;
    unsigned long long wpk[N_INP];
    unsigned long long b1pk = 0ull;
    if (active) {
        beta = sigm(tau_n[n]);   omb  = 1.0f - beta;
        a1   = sigm(tau_m1[n]);  oma1 = 1.0f - a1;
        b1pk = pack_dup(b1[n]);
#pragma unroll
        for (int i = 0; i < N_INP; ++i)
            wpk[i] = pack_dup(W1[n * KDIM + i] * mask[n * KDIM + i]);
    } else {
#pragma unroll
        for (int i = 0; i < N_INP; ++i) wpk[i] = 0ull;
    }

    float mem1[NB] = {0.f,0.f,0.f,0.f};
    float din [NB] = {0.f,0.f,0.f,0.f};
    float spk [NB] = {0.f,0.f,0.f,0.f};
    float Us  [NB] = {0.f,0.f,0.f,0.f};
    float spk0[NB] = {0.f,0.f,0.f,0.f};
    float Wac[N_OUT][NB];
#pragma unroll
    for (int o = 0; o < N_OUT; ++o)
#pragma unroll
        for (int b = 0; b < NB; ++b) Wac[o][b] = 0.f;

    const float* xbase = x + (size_t)b0 * (T_STEPS * N_INP) + lane;
    float4 rC = make_float4(0.f,0.f,0.f,0.f), rD = rC;
    if (wid == 7) {
        float4 A, Bv;
        A.x  = XG(0,0); A.y  = XG(1,0); A.z  = XG(2,0); A.w  = XG(3,0);
        Bv.x = XG(0,1); Bv.y = XG(1,1); Bv.z = XG(2,1); Bv.w = XG(3,1);
        rC.x = XG(0,2); rC.y = XG(1,2); rC.z = XG(2,2); rC.w = XG(3,2);
        rD.x = XG(0,3); rD.y = XG(1,3); rD.z = XG(2,3); rD.w = XG(3,3);
        xs4[0 * N_INP + lane] = A;
        xs4[1 * N_INP + lane] = Bv;
    }
    __syncthreads();

    int pw = 0;
#pragma unroll 1
    for (int t = 0; t < T_STEPS; ++t) {
        int pz = pw + 1; if (pz == 3) pz = 0;
        int pr = pz + 1; if (pr == 3) pr = 0;

        if (is_comp) {
            unsigned long long acc01 = b1pk, acc23 = b1pk;
            const ulonglong2* xv = (const ulonglong2*)(xs4 + (t & 3) * N_INP);
#pragma unroll
            for (int i = 0; i < N_INP; ++i) {
                ulonglong2 kv = xv[i];
                acc01 = fma_x2(wpk[i], kv.x, acc01);
                acc23 = fma_x2(wpk[i], kv.y, acc23);
            }
            float cv[NB];
            unpack2(acc01, cv[0], cv[1]);
            unpack2(acc23, cv[2], cv[3]);

            uint4 sv = *(const uint4*)(summ + pr * 4);
            if (sv.x | sv.y | sv.z | sv.w) {
#pragma unroll
                for (int b = 0; b < NB; ++b) {
                    unsigned sb = (b == 0) ? sv.x : (b == 1) ? sv.y : (b == 2) ? sv.z : sv.w;
                    if (sb) {
#pragma unroll 1
                        for (int w = 0; w < 7; ++w) {
                            unsigned m = msk[(pr * 7 + w) * 4 + b];
                            while (m) {
                                int j = (w << 5) + __ffs(m) - 1;
                                m &= m - 1;
                                if (active)
                                    cv[b] += W1[n * KDIM + N_INP + j] *
                                             mask[n * KDIM + N_INP + j];
                            }
                        }
                    }
                }
            }

#pragma unroll
            for (int b = 0; b < NB; ++b) {
                din[b]  = fmaf(beta, din[b], omb * cv[b]);
                mem1[b] = fmaf(a1, mem1[b], oma1 * din[b]) - spk[b];
                spk[b]  = (mem1[b] > VTH) ? 1.0f : 0.0f;
            }

            unsigned bal0 = __ballot_sync(0xffffffffu, spk[0] > 0.f);
            unsigned bal1 = __ballot_sync(0xffffffffu, spk[1] > 0.f);
            unsigned bal2 = __ballot_sync(0xffffffffu, spk[2] > 0.f);
            unsigned bal3 = __ballot_sync(0xffffffffu, spk[3] > 0.f);
            if (lane < 4) {
                unsigned mw = (lane == 0) ? bal0 : (lane == 1) ? bal1
                            : (lane == 2) ? bal2 : bal3;
                msk[(pw * 7 + wid) * 4 + lane] = mw;
                if (mw) atomicOr(&summ[pw * 4 + lane], mw);
            }
            if (tid < 4) summ[pz * 4 + tid] = 0;

            if (t == 0) {
#pragma unroll
                for (int b = 0; b < NB; ++b) spk0[b] = spk[b];
            } else {
#pragma unroll
                for (int b = 0; b < NB; ++b) Us[b] += spk[b];
            }
#pragma unroll
            for (int o = 0; o < N_OUT; ++o)
#pragma unroll
                for (int b = 0; b < NB; ++b)
                    Wac[o][b] = fmaf(a2v[o], Wac[o][b], spk[b]);
        } else {
            int tp2 = t + 2, tp4 = t + 4;
            if ((t & 1) == 0) {
                if (tp2 < T_STEPS) xs4[(tp2 & 3) * N_INP + lane] = rC;
                if (tp4 < T_STEPS) {
                    rC.x = XG(0,tp4); rC.y = XG(1,tp4);
                    rC.z = XG(2,tp4); rC.w = XG(3,tp4);
                }
            } else {
                if (tp2 < T_STEPS) xs4[(tp2 & 3) * N_INP + lane] = rD;
                if (tp4 < T_STEPS) {
                    rD.x = XG(0,tp4); rD.y = XG(1,tp4);
                    rD.z = XG(2,tp4); rD.w = XG(3,tp4);
                }
            }
        }
        __syncthreads();
        pw = pz;
    }

    if (active) {
#pragma unroll
        for (int o = 0; o < N_OUT; ++o)
#pragma unroll
            for (int b = 0; b < NB; ++b)
                red[(o * NB + b) * N_HID + n] = Us[b] + a2v[o] * (spk0[b] - Wac[o][b]);
    }
    __syncthreads();

    if (tid < N_OUT * NB) {
        const int o = tid / NB;
        const int b = tid % NB;
        const float* Arow = red + tid * N_HID;
        const float* w2r  = W2 + o * N_HID;
        float s = 0.f;
#pragma unroll 8
        for (int j = 0; j < N_HID; ++j) s = fmaf(__ldg(w2r + j), Arow[j], s);

        const float a   = a2v[o];
        const float aT  = powf(a, (float)T_STEPS);
        const float amT = a - aT;
        const float Sc  = amT + (float)(T_STEPS - 1) - amT / (1.0f - a);

        out[(size_t)(b0 + b) * N_OUT + o] = (s + b2[o] * Sc) * (1.0f / (float)T_STEPS);
    }
}

extern "C" void kernel_launch(void* const* d_in, const int* in_sizes, int n_in,
                              void* d_out, int out_size) {
    const float* x      = (const float*)d_in[0];
    const float* W1     = (const float*)d_in[1];
    const float* b1     = (const float*)d_in[2];
    const float* tau_n  = (const float*)d_in[3];
    const float* tau_m1 = (const float*)d_in[4];
    const float* W2     = (const float*)d_in[5];
    const float* b2     = (const float*)d_in[6];
    const float* tau_m2 = (const float*)d_in[7];
    const float* mask   = (const float*)d_in[8];
    float*       out    = (float*)d_out;

    cudaFuncSetAttribute(snn_detect_tc,
                         cudaFuncAttributeMaxDynamicSharedMemorySize, DET_SMEM_BYTES);

    snn_detect_tc<<<B_TOT, DTHR, DET_SMEM_BYTES>>>(x, W1, b1, tau_n, tau_m1, mask);
    snn_solve_kernel<<<SCTA, NTHR>>>(x, W1, b1, tau_n, tau_m1, W2, b2, tau_m2, mask, out);
}